// round 1
// baseline (speedup 1.0000x reference)
#include <cuda_runtime.h>
#include <math.h>

#define TT   8192   // tokens = B*H*W
#define CD   1024   // channels
#define FD   1024   // ffn dim
#define NE   8      // experts
#define HWD  4096   // H*W
#define BD   2      // batch

// ---- scratch (static device allocations; no cudaMalloc allowed) ----
__device__ float g_X[TT * CD];          // [T, C] tokens row-major   (32 MB)
__device__ float g_H[TT * 2 * FD];      // per (token,slot) ffn acts (64 MB)
__device__ float g_Y[TT * 2 * CD];      // per (token,slot) outputs  (64 MB)
__device__ float g_wt[TT * 2];          // routing weights per slot
__device__ int   g_cnt[NE];             // per-expert row counts
__device__ int   g_list[NE * TT];       // per-expert entries: t*2+k

// ------------------------------------------------------------------
__global__ void reset_kernel() {
    if (threadIdx.x < NE) g_cnt[threadIdx.x] = 0;
}

// NCHW -> [T, C]
__global__ __launch_bounds__(256) void transpose_in_kernel(const float* __restrict__ hs) {
    __shared__ float tile[32][33];
    const int b = blockIdx.z, c0 = blockIdx.y * 32, s0 = blockIdx.x * 32;
    const int tx = threadIdx.x, ty = threadIdx.y;
#pragma unroll
    for (int r = 0; r < 4; r++) {
        int cc = ty + r * 8;
        tile[cc][tx] = hs[((size_t)(b * CD + c0 + cc)) * HWD + s0 + tx];
    }
    __syncthreads();
#pragma unroll
    for (int r = 0; r < 4; r++) {
        int ss = ty + r * 8;
        g_X[((size_t)(b * HWD + s0 + ss)) * CD + c0 + tx] = tile[tx][ss];
    }
}

// one warp per token: 8 logits, softmax(fp32), top-2, renorm, push lists
__global__ __launch_bounds__(256) void router_kernel(const float* __restrict__ gw) {
    __shared__ float sg[NE * CD];  // 32 KB
    const int tid = threadIdx.x;
    for (int i = tid; i < NE * CD; i += 256) sg[i] = gw[i];
    __syncthreads();

    const int warp = tid >> 5, lane = tid & 31;
    const int t = blockIdx.x * 8 + warp;

    float acc[NE];
#pragma unroll
    for (int e = 0; e < NE; e++) acc[e] = 0.f;

    const float* xr = g_X + (size_t)t * CD;
    for (int c = lane; c < CD; c += 32) {
        float xv = xr[c];
#pragma unroll
        for (int e = 0; e < NE; e++) acc[e] = fmaf(xv, sg[e * CD + c], acc[e]);
    }
#pragma unroll
    for (int e = 0; e < NE; e++) {
#pragma unroll
        for (int off = 16; off > 0; off >>= 1)
            acc[e] += __shfl_xor_sync(0xffffffffu, acc[e], off);
    }

    if (lane == 0) {
        float mx = acc[0];
#pragma unroll
        for (int e = 1; e < NE; e++) mx = fmaxf(mx, acc[e]);
        float p[NE];
#pragma unroll
        for (int e = 0; e < NE; e++) p[e] = expf(acc[e] - mx);

        // top-1 (lowest index wins ties, matches jax top_k)
        int i0 = 0; float b0 = p[0];
#pragma unroll
        for (int e = 1; e < NE; e++) if (p[e] > b0) { b0 = p[e]; i0 = e; }
        // top-2
        int i1 = (i0 == 0) ? 1 : 0; float b1 = p[i1];
#pragma unroll
        for (int e = 0; e < NE; e++)
            if (e != i0 && p[e] > b1) { b1 = p[e]; i1 = e; }

        float inv = 1.f / (b0 + b1);
        g_wt[t * 2 + 0] = b0 * inv;
        g_wt[t * 2 + 1] = b1 * inv;

        int p0 = atomicAdd(&g_cnt[i0], 1);
        g_list[i0 * TT + p0] = t * 2 + 0;
        int p1 = atomicAdd(&g_cnt[i1], 1);
        g_list[i1 * TT + p1] = t * 2 + 1;
    }
}

// H[entry, n] = gelu(X@W1^T) * (X@W3^T) for gathered rows of expert e
// tile: BM=64 rows, BN=128 ffn, BK=16; 256 thr, 4x8 per thread, dual acc
__global__ __launch_bounds__(256) void gemm1_kernel(const float* __restrict__ w1,
                                                    const float* __restrict__ w3) {
    const int e  = blockIdx.z;
    const int ne = g_cnt[e];
    const int m0 = blockIdx.y * 64;
    if (m0 >= ne) return;
    const int n0 = blockIdx.x * 128;

    __shared__ float Xs[16][65];
    __shared__ float W1s[16][132];
    __shared__ float W3s[16][132];
    __shared__ int rows[64];
    __shared__ int tok[64];

    const int tid = threadIdx.x;
    if (tid < 64) {
        int i  = m0 + tid;
        int ic = (i < ne) ? i : (ne - 1);
        int entry = g_list[e * TT + ic];
        rows[tid] = (i < ne) ? entry : -1;
        tok[tid]  = entry >> 1;
    }
    __syncthreads();

    const float* W1p = w1 + (size_t)e * FD * CD;
    const float* W3p = w3 + (size_t)e * FD * CD;

    float acc1[4][8], acc3[4][8];
#pragma unroll
    for (int i = 0; i < 4; i++)
#pragma unroll
        for (int j = 0; j < 8; j++) { acc1[i][j] = 0.f; acc3[i][j] = 0.f; }

    const int lm  = tid >> 4;        // 0..15
    const int lk  = tid & 15;        // 0..15
    const int wk4 = (tid & 3) * 4;   // 0,4,8,12
    const int wn  = tid >> 2;        // 0..63
    const int ty  = tid >> 4;
    const int tx  = tid & 15;

    for (int k0 = 0; k0 < CD; k0 += 16) {
#pragma unroll
        for (int mm = 0; mm < 4; mm++) {
            int m = mm * 16 + lm;
            Xs[lk][m] = g_X[(size_t)tok[m] * CD + k0 + lk];
        }
#pragma unroll
        for (int nn = 0; nn < 2; nn++) {
            int n = nn * 64 + wn;
            const float4 v1 = *reinterpret_cast<const float4*>(W1p + (size_t)(n0 + n) * CD + k0 + wk4);
            const float4 v3 = *reinterpret_cast<const float4*>(W3p + (size_t)(n0 + n) * CD + k0 + wk4);
            W1s[wk4 + 0][n] = v1.x; W1s[wk4 + 1][n] = v1.y;
            W1s[wk4 + 2][n] = v1.z; W1s[wk4 + 3][n] = v1.w;
            W3s[wk4 + 0][n] = v3.x; W3s[wk4 + 1][n] = v3.y;
            W3s[wk4 + 2][n] = v3.z; W3s[wk4 + 3][n] = v3.w;
        }
        __syncthreads();
#pragma unroll
        for (int k = 0; k < 16; k++) {
            float a[4], b1v[8], b3v[8];
#pragma unroll
            for (int i = 0; i < 4; i++) a[i] = Xs[k][i * 16 + ty];
#pragma unroll
            for (int j = 0; j < 8; j++) { b1v[j] = W1s[k][j * 16 + tx]; b3v[j] = W3s[k][j * 16 + tx]; }
#pragma unroll
            for (int i = 0; i < 4; i++)
#pragma unroll
                for (int j = 0; j < 8; j++) {
                    acc1[i][j] = fmaf(a[i], b1v[j], acc1[i][j]);
                    acc3[i][j] = fmaf(a[i], b3v[j], acc3[i][j]);
                }
        }
        __syncthreads();
    }

#pragma unroll
    for (int i = 0; i < 4; i++) {
        int mi = i * 16 + ty;
        int entry = rows[mi];
        if (entry < 0) continue;
        float* Hrow = g_H + (size_t)entry * FD + n0;
#pragma unroll
        for (int j = 0; j < 8; j++) {
            float v = acc1[i][j];
            float g = 0.5f * v * (1.f + erff(v * 0.70710678118654752f));  // exact GELU
            Hrow[j * 16 + tx] = g * acc3[i][j];
        }
    }
}

// Y[entry, c] = wt[entry] * (H[entry] @ W2^T)
__global__ __launch_bounds__(256) void gemm2_kernel(const float* __restrict__ w2) {
    const int e  = blockIdx.z;
    const int ne = g_cnt[e];
    const int m0 = blockIdx.y * 64;
    if (m0 >= ne) return;
    const int n0 = blockIdx.x * 128;

    __shared__ float Hs[16][65];
    __shared__ float W2s[16][132];
    __shared__ int rows[64];
    __shared__ int hsrc[64];

    const int tid = threadIdx.x;
    if (tid < 64) {
        int i  = m0 + tid;
        int ic = (i < ne) ? i : (ne - 1);
        int entry = g_list[e * TT + ic];
        rows[tid] = (i < ne) ? entry : -1;
        hsrc[tid] = entry;
    }
    __syncthreads();

    const float* W2p = w2 + (size_t)e * CD * FD;

    float acc[4][8];
#pragma unroll
    for (int i = 0; i < 4; i++)
#pragma unroll
        for (int j = 0; j < 8; j++) acc[i][j] = 0.f;

    const int lm  = tid >> 4;
    const int lk  = tid & 15;
    const int wk4 = (tid & 3) * 4;
    const int wn  = tid >> 2;
    const int ty  = tid >> 4;
    const int tx  = tid & 15;

    for (int k0 = 0; k0 < FD; k0 += 16) {
#pragma unroll
        for (int mm = 0; mm < 4; mm++) {
            int m = mm * 16 + lm;
            Hs[lk][m] = g_H[(size_t)hsrc[m] * FD + k0 + lk];
        }
#pragma unroll
        for (int nn = 0; nn < 2; nn++) {
            int n = nn * 64 + wn;
            const float4 v = *reinterpret_cast<const float4*>(W2p + (size_t)(n0 + n) * FD + k0 + wk4);
            W2s[wk4 + 0][n] = v.x; W2s[wk4 + 1][n] = v.y;
            W2s[wk4 + 2][n] = v.z; W2s[wk4 + 3][n] = v.w;
        }
        __syncthreads();
#pragma unroll
        for (int k = 0; k < 16; k++) {
            float a[4], bv[8];
#pragma unroll
            for (int i = 0; i < 4; i++) a[i] = Hs[k][i * 16 + ty];
#pragma unroll
            for (int j = 0; j < 8; j++) bv[j] = W2s[k][j * 16 + tx];
#pragma unroll
            for (int i = 0; i < 4; i++)
#pragma unroll
                for (int j = 0; j < 8; j++)
                    acc[i][j] = fmaf(a[i], bv[j], acc[i][j]);
        }
        __syncthreads();
    }

#pragma unroll
    for (int i = 0; i < 4; i++) {
        int mi = i * 16 + ty;
        int entry = rows[mi];
        if (entry < 0) continue;
        float wgt = g_wt[entry];
        float* Yrow = g_Y + (size_t)entry * CD + n0;
#pragma unroll
        for (int j = 0; j < 8; j++)
            Yrow[j * 16 + tx] = wgt * acc[i][j];
    }
}

// sum the two slots, transpose back to NCHW
__global__ __launch_bounds__(256) void combine_out_kernel(float* __restrict__ out) {
    __shared__ float tile[32][33];
    const int b = blockIdx.z, c0 = blockIdx.y * 32, s0 = blockIdx.x * 32;
    const int tx = threadIdx.x, ty = threadIdx.y;
#pragma unroll
    for (int r = 0; r < 4; r++) {
        int ss = ty + r * 8;
        size_t t2 = (size_t)(b * HWD + s0 + ss) * 2;
        tile[ss][tx] = g_Y[t2 * CD + c0 + tx] + g_Y[(t2 + 1) * CD + c0 + tx];
    }
    __syncthreads();
#pragma unroll
    for (int r = 0; r < 4; r++) {
        int cc = ty + r * 8;
        out[((size_t)(b * CD + c0 + cc)) * HWD + s0 + tx] = tile[tx][cc];
    }
}

// ------------------------------------------------------------------
extern "C" void kernel_launch(void* const* d_in, const int* in_sizes, int n_in,
                              void* d_out, int out_size) {
    const float* hs   = (const float*)d_in[0];
    const float* gate = (const float*)d_in[1];
    const float* w1   = (const float*)d_in[2];
    const float* w2   = (const float*)d_in[3];
    const float* w3   = (const float*)d_in[4];
    float* out = (float*)d_out;

    reset_kernel<<<1, 32>>>();
    transpose_in_kernel<<<dim3(HWD / 32, CD / 32, BD), dim3(32, 8)>>>(hs);
    router_kernel<<<TT / 8, 256>>>(gate);
    gemm1_kernel<<<dim3(FD / 128, TT / 64, NE), 256>>>(w1, w3);
    gemm2_kernel<<<dim3(CD / 128, TT / 64, NE), 256>>>(w2);
    combine_out_kernel<<<dim3(HWD / 32, CD / 32, BD), dim3(32, 8)>>>(out);
}

// round 5
// speedup vs baseline: 2.6352x; 2.6352x over previous
#include <cuda_runtime.h>
#include <cuda_bf16.h>
#include <math.h>
#include <stdint.h>

#define TT   8192
#define CD   1024
#define FD   1024
#define NE   8
#define HWD  4096
#define BD   2
#define NENT (TT*2)

// ---------------- scratch (16B-aligned for cp.async / vector ld-st) ----------------
__device__ __align__(16) float         g_X  [TT * CD];
__device__ __align__(16) __nv_bfloat16 g_Xh [TT * CD];
__device__ __align__(16) __nv_bfloat16 g_Xl [TT * CD];
__device__ __align__(16) __nv_bfloat16 g_W1h[NE * FD * CD];
__device__ __align__(16) __nv_bfloat16 g_W1l[NE * FD * CD];
__device__ __align__(16) __nv_bfloat16 g_W3h[NE * FD * CD];
__device__ __align__(16) __nv_bfloat16 g_W3l[NE * FD * CD];
__device__ __align__(16) __nv_bfloat16 g_W2h[NE * CD * FD];
__device__ __align__(16) __nv_bfloat16 g_W2l[NE * CD * FD];
__device__ __align__(16) __nv_bfloat16 g_Hh [NENT * FD];
__device__ __align__(16) __nv_bfloat16 g_Hl [NENT * FD];
__device__ __align__(16) float         g_Y  [NENT * CD];
__device__ __align__(16) float         g_wt [NENT];
__device__ int           g_cnt[NE];
__device__ __align__(16) int           g_list[NE * TT];
__device__ __align__(16) int           g_tile_e[160];
__device__ __align__(16) int           g_tile_m0[160];
__device__ int           g_ntiles;

// ---------------- helpers ----------------
__device__ __forceinline__ uint32_t smem_u32(const void* p) {
    uint32_t a;
    asm("{ .reg .u64 t; cvta.to.shared.u64 t, %1; cvt.u32.u64 %0, t; }" : "=r"(a) : "l"(p));
    return a;
}
__device__ __forceinline__ void cp16(uint32_t dst, const void* src) {
    asm volatile("cp.async.cg.shared.global [%0], [%1], 16;" :: "r"(dst), "l"(src) : "memory");
}
#define CP_COMMIT() asm volatile("cp.async.commit_group;" ::: "memory")
#define CP_WAIT1()  asm volatile("cp.async.wait_group 1;" ::: "memory")
#define CP_WAIT0()  asm volatile("cp.async.wait_group 0;" ::: "memory")

__device__ __forceinline__ void ldsm4(uint32_t* r, uint32_t a) {
    asm volatile("ldmatrix.sync.aligned.m8n8.x4.shared.b16 {%0,%1,%2,%3}, [%4];"
        : "=r"(r[0]), "=r"(r[1]), "=r"(r[2]), "=r"(r[3]) : "r"(a));
}
__device__ __forceinline__ void mma_bf16(float* c, const uint32_t* a, const uint32_t* b) {
    asm volatile(
        "mma.sync.aligned.m16n8k16.row.col.f32.bf16.bf16.f32 "
        "{%0,%1,%2,%3}, {%4,%5,%6,%7}, {%8,%9}, {%0,%1,%2,%3};"
        : "+f"(c[0]), "+f"(c[1]), "+f"(c[2]), "+f"(c[3])
        : "r"(a[0]), "r"(a[1]), "r"(a[2]), "r"(a[3]), "r"(b[0]), "r"(b[1]));
}
__device__ __forceinline__ void split_bf16(float f, __nv_bfloat16& h, __nv_bfloat16& l) {
    h = __float2bfloat16(f);
    l = __float2bfloat16(f - __bfloat162float(h));
}

// smem stage layout (bytes), stage size 40960, two stages
#define A_H   0
#define A_L   10240
#define B_0H  20480
#define B_0L  25600
#define B_1H  30720
#define B_1L  35840
#define STG   40960
#define DSM   (2*STG)

// ------------------------------------------------------------------
__global__ void reset_kernel() { if (threadIdx.x < NE) g_cnt[threadIdx.x] = 0; }

// NCHW -> [T,C]: fp32 (router) + bf16 hi/lo planes
__global__ __launch_bounds__(256) void transpose_pack_kernel(const float* __restrict__ hs) {
    __shared__ float tile[32][33];
    const int b = blockIdx.z, c0 = blockIdx.y * 32, s0 = blockIdx.x * 32;
    const int tx = threadIdx.x, ty = threadIdx.y;
#pragma unroll
    for (int r = 0; r < 4; r++) {
        int cc = ty + r * 8;
        tile[cc][tx] = hs[((size_t)(b * CD + c0 + cc)) * HWD + s0 + tx];
    }
    __syncthreads();
#pragma unroll
    for (int r = 0; r < 4; r++) {
        int ss = ty + r * 8;
        float v = tile[tx][ss];
        size_t idx = ((size_t)(b * HWD + s0 + ss)) * CD + c0 + tx;
        g_X[idx] = v;
        __nv_bfloat16 h, l; split_bf16(v, h, l);
        g_Xh[idx] = h; g_Xl[idx] = l;
    }
}

__global__ __launch_bounds__(256) void prep_w1(const float* __restrict__ s) {
    size_t i = ((size_t)blockIdx.x * 256 + threadIdx.x) * 4;
    float4 v = *(const float4*)(s + i);
    __nv_bfloat16 h, l;
    split_bf16(v.x, h, l); g_W1h[i+0]=h; g_W1l[i+0]=l;
    split_bf16(v.y, h, l); g_W1h[i+1]=h; g_W1l[i+1]=l;
    split_bf16(v.z, h, l); g_W1h[i+2]=h; g_W1l[i+2]=l;
    split_bf16(v.w, h, l); g_W1h[i+3]=h; g_W1l[i+3]=l;
}
__global__ __launch_bounds__(256) void prep_w3(const float* __restrict__ s) {
    size_t i = ((size_t)blockIdx.x * 256 + threadIdx.x) * 4;
    float4 v = *(const float4*)(s + i);
    __nv_bfloat16 h, l;
    split_bf16(v.x, h, l); g_W3h[i+0]=h; g_W3l[i+0]=l;
    split_bf16(v.y, h, l); g_W3h[i+1]=h; g_W3l[i+1]=l;
    split_bf16(v.z, h, l); g_W3h[i+2]=h; g_W3l[i+2]=l;
    split_bf16(v.w, h, l); g_W3h[i+3]=h; g_W3l[i+3]=l;
}
__global__ __launch_bounds__(256) void prep_w2(const float* __restrict__ s) {
    size_t i = ((size_t)blockIdx.x * 256 + threadIdx.x) * 4;
    float4 v = *(const float4*)(s + i);
    __nv_bfloat16 h, l;
    split_bf16(v.x, h, l); g_W2h[i+0]=h; g_W2l[i+0]=l;
    split_bf16(v.y, h, l); g_W2h[i+1]=h; g_W2l[i+1]=l;
    split_bf16(v.z, h, l); g_W2h[i+2]=h; g_W2l[i+2]=l;
    split_bf16(v.w, h, l); g_W2h[i+3]=h; g_W2l[i+3]=l;
}

// router: warp per token
__global__ __launch_bounds__(256) void router_kernel(const float* __restrict__ gw) {
    __shared__ float sg[NE * CD];
    const int tid = threadIdx.x;
    for (int i = tid; i < NE * CD; i += 256) sg[i] = gw[i];
    __syncthreads();
    const int warp = tid >> 5, lane = tid & 31;
    const int t = blockIdx.x * 8 + warp;

    float acc[NE];
#pragma unroll
    for (int e = 0; e < NE; e++) acc[e] = 0.f;
    const float* xr = g_X + (size_t)t * CD;
    for (int c = lane; c < CD; c += 32) {
        float xv = xr[c];
#pragma unroll
        for (int e = 0; e < NE; e++) acc[e] = fmaf(xv, sg[e * CD + c], acc[e]);
    }
#pragma unroll
    for (int e = 0; e < NE; e++)
#pragma unroll
        for (int off = 16; off > 0; off >>= 1)
            acc[e] += __shfl_xor_sync(0xffffffffu, acc[e], off);

    if (lane == 0) {
        float mx = acc[0];
#pragma unroll
        for (int e = 1; e < NE; e++) mx = fmaxf(mx, acc[e]);
        float p[NE];
#pragma unroll
        for (int e = 0; e < NE; e++) p[e] = expf(acc[e] - mx);
        int i0 = 0; float b0 = p[0];
#pragma unroll
        for (int e = 1; e < NE; e++) if (p[e] > b0) { b0 = p[e]; i0 = e; }
        int i1 = (i0 == 0) ? 1 : 0; float b1 = p[i1];
#pragma unroll
        for (int e = 0; e < NE; e++)
            if (e != i0 && p[e] > b1) { b1 = p[e]; i1 = e; }
        float inv = 1.f / (b0 + b1);
        g_wt[t * 2 + 0] = b0 * inv;
        g_wt[t * 2 + 1] = b1 * inv;
        int p0 = atomicAdd(&g_cnt[i0], 1);
        g_list[i0 * TT + p0] = t * 2 + 0;
        int p1 = atomicAdd(&g_cnt[i1], 1);
        g_list[i1 * TT + p1] = t * 2 + 1;
    }
}

__global__ void schedule_kernel() {
    if (threadIdx.x == 0) {
        int nt = 0;
        for (int e = 0; e < NE; e++) {
            int c = g_cnt[e];
            for (int m0 = 0; m0 < c; m0 += 128) { g_tile_e[nt] = e; g_tile_m0[nt] = m0; nt++; }
        }
        g_ntiles = nt;
    }
}

// ---- tile loaders (cp.async) ----
// A: 128 rows x 32 k, hi+lo -> 1024 16B segs (4 iters x 256 thr)
__device__ __forceinline__ void load_A(uint32_t sbase, const __nv_bfloat16* __restrict__ srcH,
                                       const __nv_bfloat16* __restrict__ srcL, int kstride,
                                       const int* asrc, int k0, int tid) {
#pragma unroll
    for (int i = 0; i < 4; i++) {
        int seg = tid + i * 256;          // 0..1023
        int plane = seg >> 9;             // 0..1
        int rem = seg & 511;              // 0..511
        int row = rem >> 2, q = rem & 3;  // row 0..127, q 0..3
        const __nv_bfloat16* src = (plane ? srcL : srcH) + (size_t)asrc[row] * kstride + k0 + q * 8;
        cp16(sbase + (plane ? A_L : A_H) + row * 80 + q * 16, src);
    }
}
// B gemm1: two 64-row matrices (W1,W3) hi+lo -> 1024 16B segs (4 iters x 256 thr)
__device__ __forceinline__ void load_B1(uint32_t sbase, int e, int n0, int k0, int tid) {
#pragma unroll
    for (int i = 0; i < 4; i++) {
        int seg = tid + i * 256;          // 0..1023
        int mat = seg >> 9;               // 0..1
        int plane = (seg >> 8) & 1;       // 0..1
        int rem = seg & 255;              // 0..255
        int row = rem >> 2, q = rem & 3;  // row 0..63, q 0..3
        const __nv_bfloat16* base = mat ? (plane ? g_W3l : g_W3h) : (plane ? g_W1l : g_W1h);
        const __nv_bfloat16* src = base + ((size_t)e * FD + n0 + row) * CD + k0 + q * 8;
        cp16(sbase + B_0H + mat * 10240 + plane * 5120 + row * 80 + q * 16, src);
    }
}
// B gemm2: one 128-row matrix hi+lo -> 1024 segs
__device__ __forceinline__ void load_B2(uint32_t sbase, int e, int n0, int k0, int tid) {
#pragma unroll
    for (int i = 0; i < 4; i++) {
        int seg = tid + i * 256;
        int plane = seg >> 9;
        int rem = seg & 511;
        int row = rem >> 2, q = rem & 3;  // row 0..127
        const __nv_bfloat16* base = plane ? g_W2l : g_W2h;
        const __nv_bfloat16* src = base + ((size_t)e * CD + n0 + row) * FD + k0 + q * 8;
        cp16(sbase + B_0H + plane * 10240 + row * 80 + q * 16, src);
    }
}

// ---- warp compute for one 32-k chunk: m32 x n64, 3-split ----
__device__ __forceinline__ void chunk_mma(uint32_t sbase, int bOffH, int bOffL,
                                          int mb, int lane, float acc[2][8][4]) {
    const int arow = lane & 15, akoff = ((lane >> 4) & 1) * 8;
    const int brow = ((lane >> 4) & 1) * 8 + (lane & 7);
    const int bkoff = ((lane >> 3) & 1) * 8;
#pragma unroll
    for (int kb = 0; kb < 32; kb += 16) {
        uint32_t ah[2][4], al[2][4];
#pragma unroll
        for (int mi = 0; mi < 2; mi++) {
            uint32_t off = (uint32_t)((mb + mi * 16 + arow) * 80 + (kb + akoff) * 2);
            ldsm4(ah[mi], sbase + A_H + off);
            ldsm4(al[mi], sbase + A_L + off);
        }
        uint32_t bh[8][2], bl[8][2];
#pragma unroll
        for (int n4 = 0; n4 < 4; n4++) {
            uint32_t off = (uint32_t)((n4 * 16 + brow) * 80 + (kb + bkoff) * 2);
            uint32_t t[4];
            ldsm4(t, sbase + bOffH + off);
            bh[2*n4][0]=t[0]; bh[2*n4][1]=t[1]; bh[2*n4+1][0]=t[2]; bh[2*n4+1][1]=t[3];
            ldsm4(t, sbase + bOffL + off);
            bl[2*n4][0]=t[0]; bl[2*n4][1]=t[1]; bl[2*n4+1][0]=t[2]; bl[2*n4+1][1]=t[3];
        }
#pragma unroll
        for (int mi = 0; mi < 2; mi++)
#pragma unroll
            for (int ni = 0; ni < 8; ni++) {
                mma_bf16(acc[mi][ni], ah[mi], bh[ni]);
                mma_bf16(acc[mi][ni], ah[mi], bl[ni]);
                mma_bf16(acc[mi][ni], al[mi], bh[ni]);
            }
    }
}

// ------------------------------------------------------------------
// GEMM1: 128 rows x 64 ffn cols; warps 0-3 -> W1, warps 4-7 -> W3
__global__ __launch_bounds__(256, 1) void gemm1_mma() {
    if (blockIdx.y >= g_ntiles) return;
    extern __shared__ char dsm[];
    __shared__ int rows[128];
    __shared__ int asrc[128];

    const int tid = threadIdx.x, warp = tid >> 5, lane = tid & 31;
    const int e  = g_tile_e[blockIdx.y];
    const int m0 = g_tile_m0[blockIdx.y];
    const int ne = g_cnt[e];
    const int n0 = blockIdx.x * 64;

    if (tid < 128) {
        int i = m0 + tid;
        int ic = (i < ne) ? i : ne - 1;
        int entry = g_list[e * TT + ic];
        rows[tid] = (i < ne) ? entry : -1;
        asrc[tid] = entry >> 1;
    }
    __syncthreads();

    const uint32_t sb = smem_u32(dsm);
    const int mb = (warp & 3) * 32;
    const bool isW3 = warp >= 4;
    const int bOffH = isW3 ? B_1H : B_0H;
    const int bOffL = isW3 ? B_1L : B_0L;

    float acc[2][8][4];
#pragma unroll
    for (int i = 0; i < 2; i++)
#pragma unroll
        for (int j = 0; j < 8; j++)
#pragma unroll
            for (int q = 0; q < 4; q++) acc[i][j][q] = 0.f;

    load_A(sb, g_Xh, g_Xl, CD, asrc, 0, tid);
    load_B1(sb, e, n0, 0, tid);
    CP_COMMIT();
    for (int ch = 0; ch < 32; ch++) {
        if (ch + 1 < 32) {
            uint32_t nb = sb + ((ch + 1) & 1) * STG;
            load_A(nb, g_Xh, g_Xl, CD, asrc, (ch + 1) * 32, tid);
            load_B1(nb, e, n0, (ch + 1) * 32, tid);
            CP_COMMIT();
            CP_WAIT1();
        } else {
            CP_WAIT0();
        }
        __syncthreads();
        chunk_mma(sb + (ch & 1) * STG, bOffH, bOffL, mb, lane, acc);
        __syncthreads();
    }

    // epilogue: exchange P1/P3 via smem, gelu*mul, split-store H
    float* P1 = (float*)dsm;
    float* P3 = (float*)(dsm + 33792);
    float* myP = isW3 ? P3 : P1;
#pragma unroll
    for (int mi = 0; mi < 2; mi++)
#pragma unroll
        for (int ni = 0; ni < 8; ni++) {
            int m = mb + mi * 16 + (lane >> 2);
            int n = ni * 8 + (lane & 3) * 2;
            myP[m * 66 + n]       = acc[mi][ni][0];
            myP[m * 66 + n + 1]   = acc[mi][ni][1];
            myP[(m+8) * 66 + n]   = acc[mi][ni][2];
            myP[(m+8) * 66 + n+1] = acc[mi][ni][3];
        }
    __syncthreads();
    for (int idx = tid; idx < 128 * 64; idx += 256) {
        int m = idx >> 6, n = idx & 63;
        int entry = rows[m];
        if (entry < 0) continue;
        float d1 = P1[m * 66 + n];
        float d3 = P3[m * 66 + n];
        float gl = 0.5f * d1 * (1.f + erff(d1 * 0.70710678118654752f)) * d3;
        __nv_bfloat16 h, l; split_bf16(gl, h, l);
        size_t o = (size_t)entry * FD + n0 + n;
        g_Hh[o] = h; g_Hl[o] = l;
    }
}

// GEMM2: 128 rows x 128 out cols; warp grid 4(m) x 2(n)
__global__ __launch_bounds__(256, 1) void gemm2_mma() {
    if (blockIdx.y >= g_ntiles) return;
    extern __shared__ char dsm[];
    __shared__ int rows[128];
    __shared__ int asrc[128];
    __shared__ float wts[128];

    const int tid = threadIdx.x, warp = tid >> 5, lane = tid & 31;
    const int e  = g_tile_e[blockIdx.y];
    const int m0 = g_tile_m0[blockIdx.y];
    const int ne = g_cnt[e];
    const int n0 = blockIdx.x * 128;

    if (tid < 128) {
        int i = m0 + tid;
        int ic = (i < ne) ? i : ne - 1;
        int entry = g_list[e * TT + ic];
        rows[tid] = (i < ne) ? entry : -1;
        asrc[tid] = entry;
        wts[tid] = (i < ne) ? g_wt[entry] : 0.f;
    }
    __syncthreads();

    const uint32_t sb = smem_u32(dsm);
    const int mb = (warp >> 1) * 32;
    const int nb = (warp & 1) * 64;
    const int bOffH = B_0H + (nb ? 5120 : 0);
    const int bOffL = B_0H + 10240 + (nb ? 5120 : 0);

    float acc[2][8][4];
#pragma unroll
    for (int i = 0; i < 2; i++)
#pragma unroll
        for (int j = 0; j < 8; j++)
#pragma unroll
            for (int q = 0; q < 4; q++) acc[i][j][q] = 0.f;

    load_A(sb, g_Hh, g_Hl, FD, asrc, 0, tid);
    load_B2(sb, e, n0, 0, tid);
    CP_COMMIT();
    for (int ch = 0; ch < 32; ch++) {
        if (ch + 1 < 32) {
            uint32_t nbuf = sb + ((ch + 1) & 1) * STG;
            load_A(nbuf, g_Hh, g_Hl, FD, asrc, (ch + 1) * 32, tid);
            load_B2(nbuf, e, n0, (ch + 1) * 32, tid);
            CP_COMMIT();
            CP_WAIT1();
        } else {
            CP_WAIT0();
        }
        __syncthreads();
        chunk_mma(sb + (ch & 1) * STG, bOffH, bOffL, mb, lane, acc);
        __syncthreads();
    }

    // epilogue: scale by routing weight, store Y directly
#pragma unroll
    for (int mi = 0; mi < 2; mi++) {
        int mB = mb + mi * 16 + (lane >> 2);
#pragma unroll
        for (int half = 0; half < 2; half++) {
            int m = mB + half * 8;
            int entry = rows[m];
            if (entry < 0) continue;
            float w = wts[m];
            float* yr = g_Y + (size_t)entry * CD + n0 + nb;
#pragma unroll
            for (int ni = 0; ni < 8; ni++) {
                int n = ni * 8 + (lane & 3) * 2;
                float2 v = make_float2(w * acc[mi][ni][half * 2], w * acc[mi][ni][half * 2 + 1]);
                *(float2*)(yr + n) = v;
            }
        }
    }
}

// sum two slots, transpose back to NCHW
__global__ __launch_bounds__(256) void combine_out_kernel(float* __restrict__ out) {
    __shared__ float tile[32][33];
    const int b = blockIdx.z, c0 = blockIdx.y * 32, s0 = blockIdx.x * 32;
    const int tx = threadIdx.x, ty = threadIdx.y;
#pragma unroll
    for (int r = 0; r < 4; r++) {
        int ss = ty + r * 8;
        size_t t2 = (size_t)(b * HWD + s0 + ss) * 2;
        tile[ss][tx] = g_Y[t2 * CD + c0 + tx] + g_Y[(t2 + 1) * CD + c0 + tx];
    }
    __syncthreads();
#pragma unroll
    for (int r = 0; r < 4; r++) {
        int cc = ty + r * 8;
        out[((size_t)(b * CD + c0 + cc)) * HWD + s0 + tx] = tile[tx][cc];
    }
}

// ------------------------------------------------------------------
extern "C" void kernel_launch(void* const* d_in, const int* in_sizes, int n_in,
                              void* d_out, int out_size) {
    const float* hs   = (const float*)d_in[0];
    const float* gate = (const float*)d_in[1];
    const float* w1   = (const float*)d_in[2];
    const float* w2   = (const float*)d_in[3];
    const float* w3   = (const float*)d_in[4];
    float* out = (float*)d_out;

    cudaFuncSetAttribute(gemm1_mma, cudaFuncAttributeMaxDynamicSharedMemorySize, DSM);
    cudaFuncSetAttribute(gemm2_mma, cudaFuncAttributeMaxDynamicSharedMemorySize, DSM);

    reset_kernel<<<1, 32>>>();
    transpose_pack_kernel<<<dim3(HWD / 32, CD / 32, BD), dim3(32, 8)>>>(hs);
    prep_w1<<<NE * FD * CD / 4 / 256, 256>>>(w1);
    prep_w3<<<NE * FD * CD / 4 / 256, 256>>>(w3);
    prep_w2<<<NE * CD * FD / 4 / 256, 256>>>(w2);
    router_kernel<<<TT / 8, 256>>>(gate);
    schedule_kernel<<<1, 32>>>();
    gemm1_mma<<<dim3(FD / 64, 136), 256, DSM>>>();
    gemm2_mma<<<dim3(CD / 128, 136), 256, DSM>>>();
    combine_out_kernel<<<dim3(HWD / 32, CD / 32, BD), dim3(32, 8)>>>(out);
}

// round 6
// speedup vs baseline: 3.3182x; 1.2592x over previous
#include <cuda_runtime.h>
#include <cuda_bf16.h>
#include <math.h>
#include <stdint.h>

#define TT   8192
#define CD   1024
#define FD   1024
#define NE   8
#define HWD  4096
#define BD   2
#define NENT (TT*2)

// ---------------- scratch (16B-aligned for cp.async / vector ld-st) ----------------
__device__ __align__(16) float         g_X  [TT * CD];
__device__ __align__(16) __nv_bfloat16 g_Xh [TT * CD];
__device__ __align__(16) __nv_bfloat16 g_Xl [TT * CD];
__device__ __align__(16) __nv_bfloat16 g_W1h[NE * FD * CD];
__device__ __align__(16) __nv_bfloat16 g_W1l[NE * FD * CD];
__device__ __align__(16) __nv_bfloat16 g_W3h[NE * FD * CD];
__device__ __align__(16) __nv_bfloat16 g_W3l[NE * FD * CD];
__device__ __align__(16) __nv_bfloat16 g_W2h[NE * CD * FD];
__device__ __align__(16) __nv_bfloat16 g_W2l[NE * CD * FD];
__device__ __align__(16) __nv_bfloat16 g_Hh [NENT * FD];
__device__ __align__(16) __nv_bfloat16 g_Hl [NENT * FD];
__device__ __align__(16) float         g_Y  [NENT * CD];
__device__ __align__(16) float         g_wt [NENT];
__device__ int           g_cnt[NE];
__device__ __align__(16) int           g_list[NE * TT];
__device__ __align__(16) int           g_tile_e[160];
__device__ __align__(16) int           g_tile_m0[160];
__device__ int           g_ntiles;

// ---------------- helpers ----------------
__device__ __forceinline__ uint32_t smem_u32(const void* p) {
    uint32_t a;
    asm("{ .reg .u64 t; cvta.to.shared.u64 t, %1; cvt.u32.u64 %0, t; }" : "=r"(a) : "l"(p));
    return a;
}
__device__ __forceinline__ void cp16(uint32_t dst, const void* src) {
    asm volatile("cp.async.cg.shared.global [%0], [%1], 16;" :: "r"(dst), "l"(src) : "memory");
}
#define CP_COMMIT() asm volatile("cp.async.commit_group;" ::: "memory")
#define CP_WAIT0()  asm volatile("cp.async.wait_group 0;" ::: "memory")

__device__ __forceinline__ void ldsm4(uint32_t* r, uint32_t a) {
    asm volatile("ldmatrix.sync.aligned.m8n8.x4.shared.b16 {%0,%1,%2,%3}, [%4];"
        : "=r"(r[0]), "=r"(r[1]), "=r"(r[2]), "=r"(r[3]) : "r"(a));
}
__device__ __forceinline__ void mma_bf16(float* c, const uint32_t* a, const uint32_t* b) {
    asm volatile(
        "mma.sync.aligned.m16n8k16.row.col.f32.bf16.bf16.f32 "
        "{%0,%1,%2,%3}, {%4,%5,%6,%7}, {%8,%9}, {%0,%1,%2,%3};"
        : "+f"(c[0]), "+f"(c[1]), "+f"(c[2]), "+f"(c[3])
        : "r"(a[0]), "r"(a[1]), "r"(a[2]), "r"(a[3]), "r"(b[0]), "r"(b[1]));
}
__device__ __forceinline__ void split_bf16(float f, __nv_bfloat16& h, __nv_bfloat16& l) {
    h = __float2bfloat16(f);
    l = __float2bfloat16(f - __bfloat162float(h));
}

// smem stage layout (bytes), stage size 40960, two stages
#define A_H   0
#define A_L   10240
#define B_0H  20480
#define B_0L  25600
#define B_1H  30720
#define B_1L  35840
#define STG   40960
#define DSM   (2*STG)

// ------------------------------------------------------------------
__global__ void reset_kernel() { if (threadIdx.x < NE) g_cnt[threadIdx.x] = 0; }

// NCHW -> [T,C]: fp32 (router) + bf16 hi/lo planes
__global__ __launch_bounds__(256) void transpose_pack_kernel(const float* __restrict__ hs) {
    __shared__ float tile[32][33];
    const int b = blockIdx.z, c0 = blockIdx.y * 32, s0 = blockIdx.x * 32;
    const int tx = threadIdx.x, ty = threadIdx.y;
#pragma unroll
    for (int r = 0; r < 4; r++) {
        int cc = ty + r * 8;
        tile[cc][tx] = hs[((size_t)(b * CD + c0 + cc)) * HWD + s0 + tx];
    }
    __syncthreads();
#pragma unroll
    for (int r = 0; r < 4; r++) {
        int ss = ty + r * 8;
        float v = tile[tx][ss];
        size_t idx = ((size_t)(b * HWD + s0 + ss)) * CD + c0 + tx;
        g_X[idx] = v;
        __nv_bfloat16 h, l; split_bf16(v, h, l);
        g_Xh[idx] = h; g_Xl[idx] = l;
    }
}

__global__ __launch_bounds__(256) void prep_w1(const float* __restrict__ s) {
    size_t i = ((size_t)blockIdx.x * 256 + threadIdx.x) * 4;
    float4 v = *(const float4*)(s + i);
    __nv_bfloat16 h, l;
    split_bf16(v.x, h, l); g_W1h[i+0]=h; g_W1l[i+0]=l;
    split_bf16(v.y, h, l); g_W1h[i+1]=h; g_W1l[i+1]=l;
    split_bf16(v.z, h, l); g_W1h[i+2]=h; g_W1l[i+2]=l;
    split_bf16(v.w, h, l); g_W1h[i+3]=h; g_W1l[i+3]=l;
}
__global__ __launch_bounds__(256) void prep_w3(const float* __restrict__ s) {
    size_t i = ((size_t)blockIdx.x * 256 + threadIdx.x) * 4;
    float4 v = *(const float4*)(s + i);
    __nv_bfloat16 h, l;
    split_bf16(v.x, h, l); g_W3h[i+0]=h; g_W3l[i+0]=l;
    split_bf16(v.y, h, l); g_W3h[i+1]=h; g_W3l[i+1]=l;
    split_bf16(v.z, h, l); g_W3h[i+2]=h; g_W3l[i+2]=l;
    split_bf16(v.w, h, l); g_W3h[i+3]=h; g_W3l[i+3]=l;
}
__global__ __launch_bounds__(256) void prep_w2(const float* __restrict__ s) {
    size_t i = ((size_t)blockIdx.x * 256 + threadIdx.x) * 4;
    float4 v = *(const float4*)(s + i);
    __nv_bfloat16 h, l;
    split_bf16(v.x, h, l); g_W2h[i+0]=h; g_W2l[i+0]=l;
    split_bf16(v.y, h, l); g_W2h[i+1]=h; g_W2l[i+1]=l;
    split_bf16(v.z, h, l); g_W2h[i+2]=h; g_W2l[i+2]=l;
    split_bf16(v.w, h, l); g_W2h[i+3]=h; g_W2l[i+3]=l;
}

// router: warp per token
__global__ __launch_bounds__(256) void router_kernel(const float* __restrict__ gw) {
    __shared__ float sg[NE * CD];
    const int tid = threadIdx.x;
    for (int i = tid; i < NE * CD; i += 256) sg[i] = gw[i];
    __syncthreads();
    const int warp = tid >> 5, lane = tid & 31;
    const int t = blockIdx.x * 8 + warp;

    float acc[NE];
#pragma unroll
    for (int e = 0; e < NE; e++) acc[e] = 0.f;
    const float* xr = g_X + (size_t)t * CD;
    for (int c = lane; c < CD; c += 32) {
        float xv = xr[c];
#pragma unroll
        for (int e = 0; e < NE; e++) acc[e] = fmaf(xv, sg[e * CD + c], acc[e]);
    }
#pragma unroll
    for (int e = 0; e < NE; e++)
#pragma unroll
        for (int off = 16; off > 0; off >>= 1)
            acc[e] += __shfl_xor_sync(0xffffffffu, acc[e], off);

    if (lane == 0) {
        float mx = acc[0];
#pragma unroll
        for (int e = 1; e < NE; e++) mx = fmaxf(mx, acc[e]);
        float p[NE];
#pragma unroll
        for (int e = 0; e < NE; e++) p[e] = expf(acc[e] - mx);
        int i0 = 0; float b0 = p[0];
#pragma unroll
        for (int e = 1; e < NE; e++) if (p[e] > b0) { b0 = p[e]; i0 = e; }
        int i1 = (i0 == 0) ? 1 : 0; float b1 = p[i1];
#pragma unroll
        for (int e = 0; e < NE; e++)
            if (e != i0 && p[e] > b1) { b1 = p[e]; i1 = e; }
        float inv = 1.f / (b0 + b1);
        g_wt[t * 2 + 0] = b0 * inv;
        g_wt[t * 2 + 1] = b1 * inv;
        int p0 = atomicAdd(&g_cnt[i0], 1);
        g_list[i0 * TT + p0] = t * 2 + 0;
        int p1 = atomicAdd(&g_cnt[i1], 1);
        g_list[i1 * TT + p1] = t * 2 + 1;
    }
}

__global__ void schedule_kernel() {
    if (threadIdx.x == 0) {
        int nt = 0;
        for (int e = 0; e < NE; e++) {
            int c = g_cnt[e];
            for (int m0 = 0; m0 < c; m0 += 128) { g_tile_e[nt] = e; g_tile_m0[nt] = m0; nt++; }
        }
        g_ntiles = nt;
    }
}

// ---- tile loaders (cp.async) ----
__device__ __forceinline__ void load_A(uint32_t sbase, const __nv_bfloat16* __restrict__ srcH,
                                       const __nv_bfloat16* __restrict__ srcL, int kstride,
                                       const int* asrc, int k0, int tid) {
#pragma unroll
    for (int i = 0; i < 4; i++) {
        int seg = tid + i * 256;
        int plane = seg >> 9;
        int rem = seg & 511;
        int row = rem >> 2, q = rem & 3;
        const __nv_bfloat16* src = (plane ? srcL : srcH) + (size_t)asrc[row] * kstride + k0 + q * 8;
        cp16(sbase + (plane ? A_L : A_H) + row * 80 + q * 16, src);
    }
}
__device__ __forceinline__ void load_B1(uint32_t sbase, int e, int n0, int k0, int tid) {
#pragma unroll
    for (int i = 0; i < 4; i++) {
        int seg = tid + i * 256;
        int mat = seg >> 9;
        int plane = (seg >> 8) & 1;
        int rem = seg & 255;
        int row = rem >> 2, q = rem & 3;
        const __nv_bfloat16* base = mat ? (plane ? g_W3l : g_W3h) : (plane ? g_W1l : g_W1h);
        const __nv_bfloat16* src = base + ((size_t)e * FD + n0 + row) * CD + k0 + q * 8;
        cp16(sbase + B_0H + mat * 10240 + plane * 5120 + row * 80 + q * 16, src);
    }
}
__device__ __forceinline__ void load_B2(uint32_t sbase, int e, int n0, int k0, int tid) {
#pragma unroll
    for (int i = 0; i < 4; i++) {
        int seg = tid + i * 256;
        int plane = seg >> 9;
        int rem = seg & 511;
        int row = rem >> 2, q = rem & 3;
        const __nv_bfloat16* base = plane ? g_W2l : g_W2h;
        const __nv_bfloat16* src = base + ((size_t)e * CD + n0 + row) * FD + k0 + q * 8;
        cp16(sbase + B_0H + plane * 10240 + row * 80 + q * 16, src);
    }
}

// ---- warp compute for one 32-k chunk: m32 x n64, 3-split ----
__device__ __forceinline__ void chunk_mma(uint32_t sbase, int bOffH, int bOffL,
                                          int mb, int lane, float acc[2][8][4]) {
    const int arow = lane & 15, akoff = ((lane >> 4) & 1) * 8;
    const int brow = ((lane >> 4) & 1) * 8 + (lane & 7);
    const int bkoff = ((lane >> 3) & 1) * 8;
#pragma unroll
    for (int kb = 0; kb < 32; kb += 16) {
        uint32_t ah[2][4], al[2][4];
#pragma unroll
        for (int mi = 0; mi < 2; mi++) {
            uint32_t off = (uint32_t)((mb + mi * 16 + arow) * 80 + (kb + akoff) * 2);
            ldsm4(ah[mi], sbase + A_H + off);
            ldsm4(al[mi], sbase + A_L + off);
        }
        uint32_t bh[8][2], bl[8][2];
#pragma unroll
        for (int n4 = 0; n4 < 4; n4++) {
            uint32_t off = (uint32_t)((n4 * 16 + brow) * 80 + (kb + bkoff) * 2);
            uint32_t t[4];
            ldsm4(t, sbase + bOffH + off);
            bh[2*n4][0]=t[0]; bh[2*n4][1]=t[1]; bh[2*n4+1][0]=t[2]; bh[2*n4+1][1]=t[3];
            ldsm4(t, sbase + bOffL + off);
            bl[2*n4][0]=t[0]; bl[2*n4][1]=t[1]; bl[2*n4+1][0]=t[2]; bl[2*n4+1][1]=t[3];
        }
#pragma unroll
        for (int mi = 0; mi < 2; mi++)
#pragma unroll
            for (int ni = 0; ni < 8; ni++) {
                mma_bf16(acc[mi][ni], ah[mi], bh[ni]);
                mma_bf16(acc[mi][ni], ah[mi], bl[ni]);
                mma_bf16(acc[mi][ni], al[mi], bh[ni]);
            }
    }
}

// ------------------------------------------------------------------
// GEMM1: 128 rows x 64 ffn cols; warps 0-3 -> W1, warps 4-7 -> W3
__global__ __launch_bounds__(256, 2) void gemm1_mma() {
    if (blockIdx.y >= g_ntiles) return;
    extern __shared__ char dsm[];
    __shared__ int rows[128];
    __shared__ int asrc[128];

    const int tid = threadIdx.x, warp = tid >> 5, lane = tid & 31;
    const int e  = g_tile_e[blockIdx.y];
    const int m0 = g_tile_m0[blockIdx.y];
    const int ne = g_cnt[e];
    const int n0 = blockIdx.x * 64;

    if (tid < 128) {
        int i = m0 + tid;
        int ic = (i < ne) ? i : ne - 1;
        int entry = g_list[e * TT + ic];
        rows[tid] = (i < ne) ? entry : -1;
        asrc[tid] = entry >> 1;
    }
    __syncthreads();

    const uint32_t sb = smem_u32(dsm);
    const int mb = (warp & 3) * 32;
    const bool isW3 = warp >= 4;
    const int bOffH = isW3 ? B_1H : B_0H;
    const int bOffL = isW3 ? B_1L : B_0L;

    float acc[2][8][4];
#pragma unroll
    for (int i = 0; i < 2; i++)
#pragma unroll
        for (int j = 0; j < 8; j++)
#pragma unroll
            for (int q = 0; q < 4; q++) acc[i][j][q] = 0.f;

    load_A(sb, g_Xh, g_Xl, CD, asrc, 0, tid);
    load_B1(sb, e, n0, 0, tid);
    CP_COMMIT();
    // single-sync pipeline: wait chunk ch -> barrier -> issue ch+1 -> compute ch
    for (int ch = 0; ch < 32; ch++) {
        CP_WAIT0();
        __syncthreads();
        if (ch + 1 < 32) {
            uint32_t nb = sb + ((ch + 1) & 1) * STG;
            load_A(nb, g_Xh, g_Xl, CD, asrc, (ch + 1) * 32, tid);
            load_B1(nb, e, n0, (ch + 1) * 32, tid);
            CP_COMMIT();
        }
        chunk_mma(sb + (ch & 1) * STG, bOffH, bOffL, mb, lane, acc);
    }
    __syncthreads();   // epilogue staging reuses both smem stages

    // epilogue: exchange P1/P3 via smem, gelu*mul, split-store H
    float* P1 = (float*)dsm;
    float* P3 = (float*)(dsm + 33792);
    float* myP = isW3 ? P3 : P1;
#pragma unroll
    for (int mi = 0; mi < 2; mi++)
#pragma unroll
        for (int ni = 0; ni < 8; ni++) {
            int m = mb + mi * 16 + (lane >> 2);
            int n = ni * 8 + (lane & 3) * 2;
            myP[m * 66 + n]       = acc[mi][ni][0];
            myP[m * 66 + n + 1]   = acc[mi][ni][1];
            myP[(m+8) * 66 + n]   = acc[mi][ni][2];
            myP[(m+8) * 66 + n+1] = acc[mi][ni][3];
        }
    __syncthreads();
    for (int idx = tid; idx < 128 * 64; idx += 256) {
        int m = idx >> 6, n = idx & 63;
        int entry = rows[m];
        if (entry < 0) continue;
        float d1 = P1[m * 66 + n];
        float d3 = P3[m * 66 + n];
        float gl = 0.5f * d1 * (1.f + erff(d1 * 0.70710678118654752f)) * d3;
        __nv_bfloat16 h, l; split_bf16(gl, h, l);
        size_t o = (size_t)entry * FD + n0 + n;
        g_Hh[o] = h; g_Hl[o] = l;
    }
}

// GEMM2: 128 rows x 128 out cols; warp grid 4(m) x 2(n)
__global__ __launch_bounds__(256, 2) void gemm2_mma() {
    if (blockIdx.y >= g_ntiles) return;
    extern __shared__ char dsm[];
    __shared__ int rows[128];
    __shared__ int asrc[128];
    __shared__ float wts[128];

    const int tid = threadIdx.x, warp = tid >> 5, lane = tid & 31;
    const int e  = g_tile_e[blockIdx.y];
    const int m0 = g_tile_m0[blockIdx.y];
    const int ne = g_cnt[e];
    const int n0 = blockIdx.x * 128;

    if (tid < 128) {
        int i = m0 + tid;
        int ic = (i < ne) ? i : ne - 1;
        int entry = g_list[e * TT + ic];
        rows[tid] = (i < ne) ? entry : -1;
        asrc[tid] = entry;
        wts[tid] = (i < ne) ? g_wt[entry] : 0.f;
    }
    __syncthreads();

    const uint32_t sb = smem_u32(dsm);
    const int mb = (warp >> 1) * 32;
    const int nb = (warp & 1) * 64;
    const int bOffH = B_0H + (nb ? 5120 : 0);
    const int bOffL = B_0H + 10240 + (nb ? 5120 : 0);

    float acc[2][8][4];
#pragma unroll
    for (int i = 0; i < 2; i++)
#pragma unroll
        for (int j = 0; j < 8; j++)
#pragma unroll
            for (int q = 0; q < 4; q++) acc[i][j][q] = 0.f;

    load_A(sb, g_Hh, g_Hl, FD, asrc, 0, tid);
    load_B2(sb, e, n0, 0, tid);
    CP_COMMIT();
    for (int ch = 0; ch < 32; ch++) {
        CP_WAIT0();
        __syncthreads();
        if (ch + 1 < 32) {
            uint32_t nbuf = sb + ((ch + 1) & 1) * STG;
            load_A(nbuf, g_Hh, g_Hl, FD, asrc, (ch + 1) * 32, tid);
            load_B2(nbuf, e, n0, (ch + 1) * 32, tid);
            CP_COMMIT();
        }
        chunk_mma(sb + (ch & 1) * STG, bOffH, bOffL, mb, lane, acc);
    }

    // epilogue: scale by routing weight, store Y directly
#pragma unroll
    for (int mi = 0; mi < 2; mi++) {
        int mB = mb + mi * 16 + (lane >> 2);
#pragma unroll
        for (int half = 0; half < 2; half++) {
            int m = mB + half * 8;
            int entry = rows[m];
            if (entry < 0) continue;
            float w = wts[m];
            float* yr = g_Y + (size_t)entry * CD + n0 + nb;
#pragma unroll
            for (int ni = 0; ni < 8; ni++) {
                int n = ni * 8 + (lane & 3) * 2;
                float2 v = make_float2(w * acc[mi][ni][half * 2], w * acc[mi][ni][half * 2 + 1]);
                *(float2*)(yr + n) = v;
            }
        }
    }
}

// sum two slots, transpose back to NCHW
__global__ __launch_bounds__(256) void combine_out_kernel(float* __restrict__ out) {
    __shared__ float tile[32][33];
    const int b = blockIdx.z, c0 = blockIdx.y * 32, s0 = blockIdx.x * 32;
    const int tx = threadIdx.x, ty = threadIdx.y;
#pragma unroll
    for (int r = 0; r < 4; r++) {
        int ss = ty + r * 8;
        size_t t2 = (size_t)(b * HWD + s0 + ss) * 2;
        tile[ss][tx] = g_Y[t2 * CD + c0 + tx] + g_Y[(t2 + 1) * CD + c0 + tx];
    }
    __syncthreads();
#pragma unroll
    for (int r = 0; r < 4; r++) {
        int cc = ty + r * 8;
        out[((size_t)(b * CD + c0 + cc)) * HWD + s0 + tx] = tile[tx][cc];
    }
}

// ------------------------------------------------------------------
extern "C" void kernel_launch(void* const* d_in, const int* in_sizes, int n_in,
                              void* d_out, int out_size) {
    const float* hs   = (const float*)d_in[0];
    const float* gate = (const float*)d_in[1];
    const float* w1   = (const float*)d_in[2];
    const float* w2   = (const float*)d_in[3];
    const float* w3   = (const float*)d_in[4];
    float* out = (float*)d_out;

    cudaFuncSetAttribute(gemm1_mma, cudaFuncAttributeMaxDynamicSharedMemorySize, DSM);
    cudaFuncSetAttribute(gemm2_mma, cudaFuncAttributeMaxDynamicSharedMemorySize, DSM);

    reset_kernel<<<1, 32>>>();
    transpose_pack_kernel<<<dim3(HWD / 32, CD / 32, BD), dim3(32, 8)>>>(hs);
    prep_w1<<<NE * FD * CD / 4 / 256, 256>>>(w1);
    prep_w3<<<NE * FD * CD / 4 / 256, 256>>>(w3);
    prep_w2<<<NE * CD * FD / 4 / 256, 256>>>(w2);
    router_kernel<<<TT / 8, 256>>>(gate);
    schedule_kernel<<<1, 32>>>();
    gemm1_mma<<<dim3(FD / 64, 136), 256, DSM>>>();
    gemm2_mma<<<dim3(CD / 128, 136), 256, DSM>>>();
    combine_out_kernel<<<dim3(HWD / 32, CD / 32, BD), dim3(32, 8)>>>(out);
}